// round 7
// baseline (speedup 1.0000x reference)
#include <cuda_runtime.h>
#include <cuda.h>
#include <cuda_bf16.h>
#include <math.h>
#include <stdint.h>

#define B 8
#define S 8192
#define H 256
#define M 64
#define DFT_KS 16
#define DFT_CH (S / DFT_KS)   // 512

// ---------------- scratch (device globals) ----------------
__device__ float2 g_ph[S];
__device__ __nv_bfloat16 g_bfh[128 * S];     // DFT basis hi  [m'][t]
__device__ __nv_bfloat16 g_bfl[128 * S];     // DFT basis lo
__device__ __nv_bfloat16 g_ubh[B * S * H];   // u hi  [b][t][h]
__device__ __nv_bfloat16 g_ubl[B * S * H];   // u lo
__device__ __nv_bfloat16 g_b2h[S * 128];     // iDFT basis hi [t][0:64 cos,64:128 -sin]
__device__ __nv_bfloat16 g_b2l[S * 128];
__device__ __nv_bfloat16 g_cvh[B * H * 128]; // conv^T hi [b][h][0:64 re,64:128 im]
__device__ __nv_bfloat16 g_cvl[B * H * 128];
__device__ __nv_bfloat16 g_skwh[H * H], g_skwl[H * H];
__device__ __nv_bfloat16 g_w1h[128 * H], g_w1l[128 * H];
__device__ __nv_bfloat16 g_w2h[H * 128], g_w2l[H * 128];
__device__ __nv_bfloat16 g_acth[B * S * H];  // gelu(conv+skip) hi
__device__ __nv_bfloat16 g_actl[B * S * H];
__device__ float  g_utr[B*M*H], g_uti[B*M*H];
__device__ float  g_sr [B*M*H], g_si [B*M*H];
__device__ float  g_part[B * 2 * DFT_KS * 16384];
__device__ float  g_mgr[64*2*4*1024], g_mgi[64*2*4*1024];

// ---------------- helpers ----------------
__device__ __forceinline__ void fma2(float2 &d, float2 a, float2 b) {
    asm("fma.rn.f32x2 %0, %1, %2, %0;"
        : "+l"(*reinterpret_cast<unsigned long long *>(&d))
        : "l"(*reinterpret_cast<unsigned long long *>(&a)),
          "l"(*reinterpret_cast<unsigned long long *>(&b)));
}
__device__ __forceinline__ float gelu(float x) {
    return 0.5f * x * (1.0f + erff(x * 0.70710678118654752f));
}
__device__ __forceinline__ uint32_t smem_u32(const void* p) {
    uint32_t a; asm("{ .reg .u64 t; cvta.to.shared.u64 t, %1; cvt.u32.u64 %0, t; }" : "=r"(a) : "l"(p));
    return a;
}
__device__ __forceinline__ void mma_bf16(float c[4], const uint32_t a[4], uint32_t b0, uint32_t b1) {
    asm volatile("mma.sync.aligned.m16n8k16.row.col.f32.bf16.bf16.f32 "
        "{%0,%1,%2,%3}, {%4,%5,%6,%7}, {%8,%9}, {%0,%1,%2,%3};"
        : "+f"(c[0]), "+f"(c[1]), "+f"(c[2]), "+f"(c[3])
        : "r"(a[0]), "r"(a[1]), "r"(a[2]), "r"(a[3]), "r"(b0), "r"(b1));
}
#define LDSM_X4(r, addr) \
    asm volatile("ldmatrix.sync.aligned.m8n8.x4.shared.b16 {%0,%1,%2,%3}, [%4];" \
        : "=r"((r)[0]), "=r"((r)[1]), "=r"((r)[2]), "=r"((r)[3]) : "r"(addr))
#define LDSM_X4_T(r, addr) \
    asm volatile("ldmatrix.sync.aligned.m8n8.x4.trans.shared.b16 {%0,%1,%2,%3}, [%4];" \
        : "=r"((r)[0]), "=r"((r)[1]), "=r"((r)[2]), "=r"((r)[3]) : "r"(addr))
#define CPA16(dst, src) \
    asm volatile("cp.async.cg.shared.global [%0], [%1], 16;" :: "r"(dst), "l"(src) : "memory")

// 3-pass error-compensated bf16 MMA: (ah+al)(bh+bl) ~= ahbh + ahbl + albh
__device__ __forceinline__ void mma3(float c[4], const uint32_t ah[4], const uint32_t al[4],
                                     uint32_t bh0, uint32_t bh1, uint32_t bl0, uint32_t bl1) {
    mma_bf16(c, ah, bh0, bh1);
    mma_bf16(c, ah, bl0, bl1);
    mma_bf16(c, al, bh0, bh1);
}
__device__ __forceinline__ void split_bf16(float v, __nv_bfloat16 &hi, __nv_bfloat16 &lo) {
    hi = __float2bfloat16(v);
    lo = __float2bfloat16(v - __bfloat162float(hi));
}
__device__ __forceinline__ uint32_t pack2h(__nv_bfloat16 a, __nv_bfloat16 b) {
    return (uint32_t)__bfloat16_as_ushort(a) | ((uint32_t)__bfloat16_as_ushort(b) << 16);
}

// ---------------- K0: tables ----------------
__global__ void k_phase() {
    int p = blockIdx.x * 256 + threadIdx.x;
    if (p >= S) return;
    float ang = (float)p * (6.283185307179586f / 8192.0f);
    float sn, cn; sincosf(ang, &sn, &cn);
    g_ph[p] = make_float2(cn, sn);
}
__global__ void k_basisF() {
    int idx = blockIdx.x * 256 + threadIdx.x;
    int mp = idx >> 13, t = idx & 8191;
    float v;
    if (mp < 64) v =  g_ph[(mp * t) & 8191].x;
    else         v = -g_ph[((mp - 64) * t) & 8191].y;
    __nv_bfloat16 hi, lo; split_bf16(v, hi, lo);
    g_bfh[idx] = hi; g_bfl[idx] = lo;
}
__global__ void k_basis2hl() {
    int idx = blockIdx.x * 256 + threadIdx.x;
    if (idx >= S * 128) return;
    int t = idx >> 7, m = idx & 127;
    float v;
    if (m < 64) v =  g_ph[(t * m) & (S - 1)].x;
    else        v = -g_ph[(t * (m - 64)) & (S - 1)].y;
    __nv_bfloat16 hi, lo; split_bf16(v, hi, lo);
    g_b2h[idx] = hi; g_b2l[idx] = lo;
}
__global__ void k_wsplit(const float *__restrict__ skw, const float *__restrict__ w1,
                         const float *__restrict__ w2) {
    int idx = blockIdx.x * 256 + threadIdx.x;   // < 131072
    float v; __nv_bfloat16 *dh, *dl; int o;
    if (idx < 65536)      { v = skw[idx];        dh = g_skwh; dl = g_skwl; o = idx; }
    else if (idx < 98304) { o = idx - 65536; v = w1[o]; dh = g_w1h; dl = g_w1l; }
    else                  { o = idx - 98304; v = w2[o]; dh = g_w2h; dl = g_w2l; }
    __nv_bfloat16 hi, lo; split_bf16(v, hi, lo);
    dh[o] = hi; dl[o] = lo;
}

// ---------------- u -> bf16 hi/lo ----------------
__global__ void k_usplit(const float *__restrict__ u) {
    size_t gid = (size_t)blockIdx.x * 256 + threadIdx.x;
    float4 v = ((const float4 *)u)[gid];
    float vv[4] = {v.x, v.y, v.z, v.w};
    uint32_t hh[2] = {0, 0}, ll[2] = {0, 0};
#pragma unroll
    for (int j = 0; j < 4; j++) {
        __nv_bfloat16 hi, lo; split_bf16(vv[j], hi, lo);
        hh[j >> 1] |= (uint32_t)__bfloat16_as_ushort(hi) << ((j & 1) * 16);
        ll[j >> 1] |= (uint32_t)__bfloat16_as_ushort(lo) << ((j & 1) * 16);
    }
    ((uint2 *)g_ubh)[gid] = make_uint2(hh[0], hh[1]);
    ((uint2 *)g_ubl)[gid] = make_uint2(ll[0], ll[1]);
}

// ---------------- DFT via bf16x2 3-pass mma + ldmatrix (proven) ----------------
#define DBUF 37888
#define DFT_SMEM (2 * DBUF)

__global__ void __launch_bounds__(256, 2) k_dftmma() {
    extern __shared__ __align__(16) char sm[];
    int tid = threadIdx.x, lane = tid & 31, w = tid >> 5;
    int wm = w & 3, wn = w >> 2, g = lane >> 2, tg = lane & 3;
    int ks = blockIdx.x, nb = blockIdx.y, b = blockIdx.z;
    int tbase0 = ks * DFT_CH;
    uint32_t s0 = smem_u32(sm);

    float acc[2][8][4];
#pragma unroll
    for (int mt = 0; mt < 2; mt++)
#pragma unroll
        for (int nt = 0; nt < 8; nt++)
#pragma unroll
            for (int q = 0; q < 4; q++) acc[mt][nt][q] = 0.f;

    auto stage = [&](int c, int buf) {
        int t0 = tbase0 + c * 32;
        uint32_t base = s0 + buf * DBUF;
#pragma unroll
        for (int it = 0; it < 2; it++) {
            int idx = it * 256 + tid;
            int r = idx >> 2, seg = idx & 3;
            uint32_t sh = base + (uint32_t)(r * 80 + seg * 16);
            CPA16(sh,         g_bfh + (size_t)r * S + t0 + seg * 8);
            CPA16(sh + 10240, g_bfl + (size_t)r * S + t0 + seg * 8);
        }
#pragma unroll
        for (int it = 0; it < 2; it++) {
            int idx = it * 256 + tid;
            int r = idx >> 4, seg = idx & 15;
            uint32_t sh = base + 20480 + (uint32_t)(r * 272 + seg * 16);
            CPA16(sh,        g_ubh + ((size_t)(b * S + t0 + r)) * 256 + nb * 128 + seg * 8);
            CPA16(sh + 8704, g_ubl + ((size_t)(b * S + t0 + r)) * 256 + nb * 128 + seg * 8);
        }
    };

    stage(0, 0);
    asm volatile("cp.async.commit_group;" ::: "memory");

    for (int c = 0; c < 16; c++) {
        int buf = c & 1;
        if (c < 15) {
            stage(c + 1, buf ^ 1);
            asm volatile("cp.async.commit_group;" ::: "memory");
            asm volatile("cp.async.wait_group 1;" ::: "memory");
        } else {
            asm volatile("cp.async.wait_group 0;" ::: "memory");
        }
        __syncthreads();

        uint32_t base = s0 + buf * DBUF;
#pragma unroll
        for (int kh = 0; kh < 2; kh++) {
            uint32_t ah[2][4], al[2][4];
#pragma unroll
            for (int mt = 0; mt < 2; mt++) {
                uint32_t ra = base + (uint32_t)((wm * 32 + mt * 16 + (lane & 15)) * 80 + kh * 32 + (lane >> 4) * 16);
                LDSM_X4(ah[mt], ra);
                LDSM_X4(al[mt], ra + 10240);
            }
#pragma unroll
            for (int ntp = 0; ntp < 4; ntp++) {
                uint32_t rb = base + 20480 +
                    (uint32_t)((kh * 16 + (lane & 7) + ((lane >> 3) & 1) * 8) * 272 +
                               (wn * 64 + ntp * 16 + (lane >> 4) * 8) * 2);
                uint32_t bh[4], bl[4];
                LDSM_X4_T(bh, rb);
                LDSM_X4_T(bl, rb + 8704);
#pragma unroll
                for (int mt = 0; mt < 2; mt++) {
                    mma3(acc[mt][2 * ntp],     ah[mt], al[mt], bh[0], bh[1], bl[0], bl[1]);
                    mma3(acc[mt][2 * ntp + 1], ah[mt], al[mt], bh[2], bh[3], bl[2], bl[3]);
                }
            }
        }
        __syncthreads();
    }

    float *pp = g_part + (size_t)((b * 2 + nb) * DFT_KS + ks) * 16384;
#pragma unroll
    for (int mt = 0; mt < 2; mt++)
#pragma unroll
        for (int nt = 0; nt < 8; nt++) {
            int row = wm * 32 + mt * 16 + g;
            int col = wn * 64 + nt * 8 + 2 * tg;
            *(float2 *)(pp + row * 128 + col)       = make_float2(acc[mt][nt][0], acc[mt][nt][1]);
            *(float2 *)(pp + (row + 8) * 128 + col) = make_float2(acc[mt][nt][2], acc[mt][nt][3]);
        }
}

__global__ void k_dftred() {
    int gid = blockIdx.x * 256 + threadIdx.x;
    int h = gid & 255, row = (gid >> 8) & 127, b = gid >> 15;
    int nb = h >> 7, cl = h & 127;
    const float *p = g_part + (size_t)((b * 2 + nb) * DFT_KS) * 16384 + row * 128 + cl;
    float s = 0.f;
#pragma unroll
    for (int ks = 0; ks < DFT_KS; ks++) s += p[(size_t)ks * 16384];
    if (row < 64) g_utr[(b * 64 + row) * 256 + h] = s;
    else          g_uti[(b * 64 + row - 64) * 256 + h] = s;
}

// ---------------- K2: per-mode complex GEMM (split-K x4) + reduce/GELU ----------------
__global__ void __launch_bounds__(256) k_modegemm(const float *__restrict__ Wr,
                                                  const float *__restrict__ Wi) {
    __shared__ float utr_s[8][256];
    __shared__ float uti_s[8][256];
    int m = blockIdx.x, half = blockIdx.y, kk = blockIdx.z;
    int tid = threadIdx.x;
#pragma unroll
    for (int i = 0; i < 8; i++) {
        int lin = i * 256 + tid; int bb = lin >> 8, h = lin & 255;
        utr_s[bb][h] = g_utr[(bb * 64 + m) * 256 + h];
        uti_s[bb][h] = g_uti[(bb * 64 + m) * 256 + h];
    }
    __syncthreads();
    int ho = half * 128 + (tid & 127);
    int bg = (tid >> 7) * 4;
    float accr[4] = {0,0,0,0}, acci[4] = {0,0,0,0};
    const float *wrp = Wr + (size_t)m * 65536 + ho;
    const float *wip = Wi + (size_t)m * 65536 + ho;
    int hk0 = kk * 64;
#pragma unroll 4
    for (int hk = hk0; hk < hk0 + 64; hk++) {
        float wr = wrp[(size_t)hk * 256], wi = wip[(size_t)hk * 256];
#pragma unroll
        for (int ib = 0; ib < 4; ib++) {
            float ur = utr_s[bg + ib][hk], ui = uti_s[bg + ib][hk];
            accr[ib] += ur * wr - ui * wi;
            acci[ib] += ur * wi + ui * wr;
        }
    }
    float *pr = g_mgr + (size_t)(((m * 2 + half) * 4) + kk) * 1024;
    float *pi = g_mgi + (size_t)(((m * 2 + half) * 4) + kk) * 1024;
#pragma unroll
    for (int ib = 0; ib < 4; ib++) {
        pr[(bg + ib) * 128 + (tid & 127)] = accr[ib];
        pi[(bg + ib) * 128 + (tid & 127)] = acci[ib];
    }
}

__global__ void k_mgred() {
    int gid = blockIdx.x * 256 + threadIdx.x;
    int h = gid & 255, m = (gid >> 8) & 63, b = gid >> 14;
    int half = h >> 7, ho = h & 127;
    size_t base = (size_t)((m * 2 + half) * 4) * 1024 + b * 128 + ho;
    float sr = 0.f, si = 0.f;
#pragma unroll
    for (int kk = 0; kk < 4; kk++) { sr += g_mgr[base + kk * 1024]; si += g_mgi[base + kk * 1024]; }
    g_sr[gid] = gelu(sr);
    g_si[gid] = gelu(si);
}

// ---------------- K3: circular convolution -> cvt hi/lo bf16 ----------------
__global__ void __launch_bounds__(256) k_conv() {
    __shared__ __align__(16) float utr_s[64][32];
    __shared__ __align__(16) float uti_s[64][32];
    __shared__ __align__(16) float sr_s[64][32];
    __shared__ __align__(16) float si_s[64][32];
    int b = blockIdx.x, ht = blockIdx.y;
    int h0 = ht * 32;
    int tid = threadIdx.x;
#pragma unroll
    for (int i = 0; i < 8; i++) {
        int lin = i * 256 + tid; int k = lin >> 5, hh = lin & 31;
        int o = (b * 64 + k) * 256 + h0 + hh;
        utr_s[k][hh] = g_utr[o]; uti_s[k][hh] = g_uti[o];
        sr_s[k][hh]  = g_sr[o];  si_s[k][hh]  = g_si[o];
    }
    __syncthreads();
    int m0 = (tid >> 4) << 2;
    int hp = tid & 15;
    float2 cr[4], ci[4];
#pragma unroll
    for (int i = 0; i < 4; i++) { cr[i] = make_float2(0.f,0.f); ci[i] = make_float2(0.f,0.f); }
    for (int k = 0; k < 64; k++) {
        float2 ua = ((float2 *)utr_s[k])[hp];
        float2 ub = ((float2 *)uti_s[k])[hp];
#pragma unroll
        for (int im = 0; im < 4; im++) {
            int j = ((m0 + im) - k) & 63;
            float2 br = ((float2 *)sr_s[j])[hp];
            float2 bi = ((float2 *)si_s[j])[hp];
            float2 nbi = make_float2(-bi.x, -bi.y);
            fma2(cr[im], ua, br);  fma2(cr[im], ub, nbi);
            fma2(ci[im], ua, bi);  fma2(ci[im], ub, br);
        }
    }
    const float SC = 1.0f / 65536.0f;
    int hA = h0 + 2 * hp, hB = hA + 1;
#pragma unroll
    for (int im = 0; im < 4; im++) {
        int m = m0 + im;
        float vals[4] = {cr[im].x * SC, cr[im].y * SC, ci[im].x * SC, ci[im].y * SC};
        int idxs[4] = {(b * 256 + hA) * 128 + m, (b * 256 + hB) * 128 + m,
                       (b * 256 + hA) * 128 + 64 + m, (b * 256 + hB) * 128 + 64 + m};
#pragma unroll
        for (int q = 0; q < 4; q++) {
            __nv_bfloat16 hi, lo; split_bf16(vals[q], hi, lo);
            g_cvh[idxs[q]] = hi; g_cvl[idxs[q]] = lo;
        }
    }
}

// ---------------- G1: iDFT + skip via bf16x2 3-pass mma ----------------
// per buffer: Ah@0 (10240), Al@10240, Bh@20480, Bl@30720  (rows x 80B, 128 rows)
#define G1BUF 40960
#define G1_SMEM (2 * G1BUF)

__global__ void __launch_bounds__(256, 2) k_g1(const float *__restrict__ skb) {
    extern __shared__ __align__(16) char sm[];
    int tid = threadIdx.x, lane = tid & 31, w = tid >> 5;
    int wm = w & 3, wn = w >> 2, g = lane >> 2, tg = lane & 3;
    int t0 = blockIdx.x * 128, n0 = blockIdx.y * 128, b = blockIdx.z;
    uint32_t s0 = smem_u32(sm);

    float acc[2][8][4];
#pragma unroll
    for (int mt = 0; mt < 2; mt++)
#pragma unroll
        for (int nt = 0; nt < 8; nt++)
#pragma unroll
            for (int q = 0; q < 4; q++) acc[mt][nt][q] = 0.f;

    auto stage = [&](int c, int buf) {
        uint32_t base = s0 + buf * G1BUF;
#pragma unroll
        for (int it = 0; it < 2; it++) {
            int idx = it * 256 + tid;
            int r = idx >> 2, seg = idx & 3;
            uint32_t sh = base + (uint32_t)(r * 80 + seg * 16);
            const __nv_bfloat16 *gh, *gl;
            if (c < 4) {
                gh = g_b2h + (size_t)(t0 + r) * 128 + c * 32 + seg * 8;
                gl = g_b2l + (size_t)(t0 + r) * 128 + c * 32 + seg * 8;
            } else {
                gh = g_ubh + ((size_t)(b * S + t0 + r)) * 256 + (c - 4) * 32 + seg * 8;
                gl = g_ubl + ((size_t)(b * S + t0 + r)) * 256 + (c - 4) * 32 + seg * 8;
            }
            CPA16(sh, gh); CPA16(sh + 10240, gl);
        }
#pragma unroll
        for (int it = 0; it < 2; it++) {
            int idx = it * 256 + tid;
            int r = idx >> 2, seg = idx & 3;
            uint32_t sh = base + 20480 + (uint32_t)(r * 80 + seg * 16);
            const __nv_bfloat16 *gh, *gl;
            if (c < 4) {
                gh = g_cvh + (size_t)(b * 256 + n0 + r) * 128 + c * 32 + seg * 8;
                gl = g_cvl + (size_t)(b * 256 + n0 + r) * 128 + c * 32 + seg * 8;
            } else {
                gh = g_skwh + (size_t)(n0 + r) * 256 + (c - 4) * 32 + seg * 8;
                gl = g_skwl + (size_t)(n0 + r) * 256 + (c - 4) * 32 + seg * 8;
            }
            CPA16(sh, gh); CPA16(sh + 10240, gl);
        }
    };

    stage(0, 0);
    asm volatile("cp.async.commit_group;" ::: "memory");

    for (int c = 0; c < 12; c++) {
        int buf = c & 1;
        if (c < 11) {
            stage(c + 1, buf ^ 1);
            asm volatile("cp.async.commit_group;" ::: "memory");
            asm volatile("cp.async.wait_group 1;" ::: "memory");
        } else {
            asm volatile("cp.async.wait_group 0;" ::: "memory");
        }
        __syncthreads();

        uint32_t base = s0 + buf * G1BUF;
#pragma unroll
        for (int kh = 0; kh < 2; kh++) {
            uint32_t ah[2][4], al[2][4];
#pragma unroll
            for (int mt = 0; mt < 2; mt++) {
                uint32_t ra = base + (uint32_t)((wm * 32 + mt * 16 + (lane & 15)) * 80 + kh * 32 + (lane >> 4) * 16);
                LDSM_X4(ah[mt], ra);
                LDSM_X4(al[mt], ra + 10240);
            }
#pragma unroll
            for (int nq = 0; nq < 4; nq++) {
                uint32_t rb = base + 20480 +
                    (uint32_t)((wn * 64 + nq * 16 + (lane & 7) + ((lane >> 4) & 1) * 8) * 80 +
                               kh * 32 + ((lane >> 3) & 1) * 16);
                uint32_t bh[4], bl[4];
                LDSM_X4(bh, rb);
                LDSM_X4(bl, rb + 10240);
#pragma unroll
                for (int mt = 0; mt < 2; mt++) {
                    mma3(acc[mt][2 * nq],     ah[mt], al[mt], bh[0], bh[1], bl[0], bl[1]);
                    mma3(acc[mt][2 * nq + 1], ah[mt], al[mt], bh[2], bh[3], bl[2], bl[3]);
                }
            }
        }
        __syncthreads();
    }

    // epilogue: gelu(+skb) -> act hi/lo bf16
#pragma unroll
    for (int mt = 0; mt < 2; mt++)
#pragma unroll
        for (int nt = 0; nt < 8; nt++) {
            int row = t0 + wm * 32 + mt * 16 + g;
            int col = n0 + wn * 64 + nt * 8 + 2 * tg;
            float bz0 = __ldg(skb + col), bz1 = __ldg(skb + col + 1);
            float v0 = gelu(acc[mt][nt][0] + bz0), v1 = gelu(acc[mt][nt][1] + bz1);
            float v2 = gelu(acc[mt][nt][2] + bz0), v3 = gelu(acc[mt][nt][3] + bz1);
            __nv_bfloat16 h0, l0, h1, l1, h2, l2, h3, l3;
            split_bf16(v0, h0, l0); split_bf16(v1, h1, l1);
            split_bf16(v2, h2, l2); split_bf16(v3, h3, l3);
            size_t o0 = ((size_t)(b * S) + row) * 256 + col;
            size_t o1 = ((size_t)(b * S) + row + 8) * 256 + col;
            *(uint32_t *)(g_acth + o0) = pack2h(h0, h1);
            *(uint32_t *)(g_actl + o0) = pack2h(l0, l1);
            *(uint32_t *)(g_acth + o1) = pack2h(h2, h3);
            *(uint32_t *)(g_actl + o1) = pack2h(l2, l3);
        }
}

// ---------------- fused G2+G3 via bf16x2 3-pass mma ----------------
// hsm_hi@0 (17408B), hsm_lo@17408; buffers @34816 + buf*30720:
//   Ah@0 (5120), Al@5120, Bh@10240 (10240), Bl@20480
#define F23_BUF0 34816
#define F23_BUFSZ 30720
#define F23_SMEM (F23_BUF0 + 2 * F23_BUFSZ)   // 96256

__global__ void __launch_bounds__(256, 2) k_f23(
    const float *__restrict__ b1, const float *__restrict__ b2,
    float *__restrict__ out) {
    extern __shared__ __align__(16) char sm[];
    int tid = threadIdx.x, lane = tid & 31, w = tid >> 5;
    int wm = w & 1, wn = w >> 1;            // 2 (m) x 4 (n)
    int g = lane >> 2, tg = lane & 3;
    int t0 = blockIdx.x * 64, b = blockIdx.y;
    uint32_t s0 = smem_u32(sm);
    uint32_t hh = s0, hl = s0 + 17408;

    float acc[2][4][4];
#pragma unroll
    for (int mt = 0; mt < 2; mt++)
#pragma unroll
        for (int nt = 0; nt < 4; nt++)
#pragma unroll
            for (int q = 0; q < 4; q++) acc[mt][nt][q] = 0.f;

    // ---------- G2: h = gelu(act @ w1^T + b1) ----------
    auto stage2 = [&](int c, int buf) {
        uint32_t base = s0 + F23_BUF0 + buf * F23_BUFSZ;
        {   // A: act 64 rows
            int r = tid >> 2, seg = tid & 3;
            uint32_t sh = base + (uint32_t)(r * 80 + seg * 16);
            size_t go = ((size_t)(b * S + t0 + r)) * 256 + c * 32 + seg * 8;
            CPA16(sh, g_acth + go); CPA16(sh + 5120, g_actl + go);
        }
#pragma unroll
        for (int it = 0; it < 2; it++) {     // B: w1 128 rows
            int idx = it * 256 + tid;
            int r = idx >> 2, seg = idx & 3;
            uint32_t sh = base + 10240 + (uint32_t)(r * 80 + seg * 16);
            size_t go = (size_t)r * 256 + c * 32 + seg * 8;
            CPA16(sh, g_w1h + go); CPA16(sh + 10240, g_w1l + go);
        }
    };

    stage2(0, 0);
    asm volatile("cp.async.commit_group;" ::: "memory");
    for (int c = 0; c < 8; c++) {
        int buf = c & 1;
        if (c < 7) {
            stage2(c + 1, buf ^ 1);
            asm volatile("cp.async.commit_group;" ::: "memory");
            asm volatile("cp.async.wait_group 1;" ::: "memory");
        } else {
            asm volatile("cp.async.wait_group 0;" ::: "memory");
        }
        __syncthreads();
        uint32_t base = s0 + F23_BUF0 + buf * F23_BUFSZ;
#pragma unroll
        for (int kh = 0; kh < 2; kh++) {
            uint32_t ah[2][4], al[2][4];
#pragma unroll
            for (int mt = 0; mt < 2; mt++) {
                uint32_t ra = base + (uint32_t)((wm * 32 + mt * 16 + (lane & 15)) * 80 + kh * 32 + (lane >> 4) * 16);
                LDSM_X4(ah[mt], ra);
                LDSM_X4(al[mt], ra + 5120);
            }
#pragma unroll
            for (int nq = 0; nq < 2; nq++) {
                uint32_t rb = base + 10240 +
                    (uint32_t)((wn * 32 + nq * 16 + (lane & 7) + ((lane >> 4) & 1) * 8) * 80 +
                               kh * 32 + ((lane >> 3) & 1) * 16);
                uint32_t bh[4], bl[4];
                LDSM_X4(bh, rb);
                LDSM_X4(bl, rb + 10240);
#pragma unroll
                for (int mt = 0; mt < 2; mt++) {
                    mma3(acc[mt][2 * nq],     ah[mt], al[mt], bh[0], bh[1], bl[0], bl[1]);
                    mma3(acc[mt][2 * nq + 1], ah[mt], al[mt], bh[2], bh[3], bl[2], bl[3]);
                }
            }
        }
        __syncthreads();
    }
    // epilogue G2 -> hsm hi/lo (stride 136 halves = 272B)
#pragma unroll
    for (int mt = 0; mt < 2; mt++)
#pragma unroll
        for (int nt = 0; nt < 4; nt++) {
            int row = wm * 32 + mt * 16 + g;
            int col = wn * 32 + nt * 8 + 2 * tg;
            float bz0 = __ldg(b1 + col), bz1 = __ldg(b1 + col + 1);
            float v0 = gelu(acc[mt][nt][0] + bz0), v1 = gelu(acc[mt][nt][1] + bz1);
            float v2 = gelu(acc[mt][nt][2] + bz0), v3 = gelu(acc[mt][nt][3] + bz1);
            __nv_bfloat16 h0, l0, h1, l1, h2, l2, h3, l3;
            split_bf16(v0, h0, l0); split_bf16(v1, h1, l1);
            split_bf16(v2, h2, l2); split_bf16(v3, h3, l3);
            uint32_t o0 = (uint32_t)(row * 272 + col * 2);
            uint32_t o1 = (uint32_t)((row + 8) * 272 + col * 2);
            asm volatile("st.shared.b32 [%0], %1;" :: "r"(hh + o0), "r"(pack2h(h0, h1)));
            asm volatile("st.shared.b32 [%0], %1;" :: "r"(hl + o0), "r"(pack2h(l0, l1)));
            asm volatile("st.shared.b32 [%0], %1;" :: "r"(hh + o1), "r"(pack2h(h2, h3)));
            asm volatile("st.shared.b32 [%0], %1;" :: "r"(hl + o1), "r"(pack2h(l2, l3)));
        }
    __syncthreads();

    // ---------- G3: out = h @ w2^T + b2, two 128-col halves ----------
    for (int nh = 0; nh < 2; nh++) {
        auto stage3 = [&](int c, int buf) {
            uint32_t base = s0 + F23_BUF0 + buf * F23_BUFSZ;
#pragma unroll
            for (int it = 0; it < 2; it++) {
                int idx = it * 256 + tid;
                int r = idx >> 2, seg = idx & 3;
                uint32_t sh = base + 10240 + (uint32_t)(r * 80 + seg * 16);
                size_t go = (size_t)(nh * 128 + r) * 128 + c * 32 + seg * 8;
                CPA16(sh, g_w2h + go); CPA16(sh + 10240, g_w2l + go);
            }
        };
#pragma unroll
        for (int mt = 0; mt < 2; mt++)
#pragma unroll
            for (int nt = 0; nt < 4; nt++)
#pragma unroll
                for (int q = 0; q < 4; q++) acc[mt][nt][q] = 0.f;

        stage3(0, 0);
        asm volatile("cp.async.commit_group;" ::: "memory");
        for (int c = 0; c < 4; c++) {
            int buf = c & 1;
            if (c < 3) {
                stage3(c + 1, buf ^ 1);
                asm volatile("cp.async.commit_group;" ::: "memory");
                asm volatile("cp.async.wait_group 1;" ::: "memory");
            } else {
                asm volatile("cp.async.wait_group 0;" ::: "memory");
            }
            __syncthreads();
            uint32_t base = s0 + F23_BUF0 + buf * F23_BUFSZ;
#pragma unroll
            for (int kh = 0; kh < 2; kh++) {
                uint32_t ah[2][4], al[2][4];
#pragma unroll
                for (int mt = 0; mt < 2; mt++) {
                    uint32_t ra = (uint32_t)((wm * 32 + mt * 16 + (lane & 15)) * 272 +
                                             c * 64 + kh * 32 + (lane >> 4) * 16);
                    LDSM_X4(ah[mt], hh + ra);
                    LDSM_X4(al[mt], hl + ra);
                }
#pragma unroll
                for (int nq = 0; nq < 2; nq++) {
                    uint32_t rb = base + 10240 +
                        (uint32_t)((wn * 32 + nq * 16 + (lane & 7) + ((lane >> 4) & 1) * 8) * 80 +
                                   kh * 32 + ((lane >> 3) & 1) * 16);
                    uint32_t bh[4], bl[4];
                    LDSM_X4(bh, rb);
                    LDSM_X4(bl, rb + 10240);
#pragma unroll
                    for (int mt = 0; mt < 2; mt++) {
                        mma3(acc[mt][2 * nq],     ah[mt], al[mt], bh[0], bh[1], bl[0], bl[1]);
                        mma3(acc[mt][2 * nq + 1], ah[mt], al[mt], bh[2], bh[3], bl[2], bl[3]);
                    }
                }
            }
            __syncthreads();
        }
        // epilogue G3 -> out
#pragma unroll
        for (int mt = 0; mt < 2; mt++)
#pragma unroll
            for (int nt = 0; nt < 4; nt++) {
                int row = t0 + wm * 32 + mt * 16 + g;
                int col = nh * 128 + wn * 32 + nt * 8 + 2 * tg;
                float bz0 = __ldg(b2 + col), bz1 = __ldg(b2 + col + 1);
                float2 v0 = make_float2(acc[mt][nt][0] + bz0, acc[mt][nt][1] + bz1);
                float2 v1 = make_float2(acc[mt][nt][2] + bz0, acc[mt][nt][3] + bz1);
                *(float2 *)(out + ((size_t)b * S + row) * 256 + col)     = v0;
                *(float2 *)(out + ((size_t)b * S + row + 8) * 256 + col) = v1;
            }
        __syncthreads();
    }
}

// ---------------- launch ----------------
extern "C" void kernel_launch(void *const *d_in, const int *in_sizes, int n_in,
                              void *d_out, int out_size) {
    const float *u   = (const float *)d_in[0];
    const float *Wr  = (const float *)d_in[1];
    const float *Wi  = (const float *)d_in[2];
    const float *skw = (const float *)d_in[3];
    const float *skb = (const float *)d_in[4];
    const float *w1  = (const float *)d_in[5];
    const float *b1  = (const float *)d_in[6];
    const float *w2  = (const float *)d_in[7];
    const float *b2  = (const float *)d_in[8];
    float *out = (float *)d_out;

    cudaFuncSetAttribute(k_dftmma, cudaFuncAttributeMaxDynamicSharedMemorySize, DFT_SMEM);
    cudaFuncSetAttribute(k_g1, cudaFuncAttributeMaxDynamicSharedMemorySize, G1_SMEM);
    cudaFuncSetAttribute(k_f23, cudaFuncAttributeMaxDynamicSharedMemorySize, F23_SMEM);

    k_phase<<<(S + 255) / 256, 256>>>();
    k_basisF<<<(128 * S) / 256, 256>>>();
    k_basis2hl<<<(S * 128) / 256, 256>>>();
    k_usplit<<<(B * S * H / 4) / 256, 256>>>(u);
    k_wsplit<<<512, 256>>>(skw, w1, w2);
    k_dftmma<<<dim3(DFT_KS, 2, B), 256, DFT_SMEM>>>();
    k_dftred<<<(B * 128 * 256) / 256, 256>>>();
    k_modegemm<<<dim3(M, 2, 4), 256>>>(Wr, Wi);
    k_mgred<<<(B * M * H) / 256, 256>>>();
    k_conv<<<dim3(B, 8), 256>>>();
    k_g1<<<dim3(S / 128, 2, B), 256, G1_SMEM>>>(skb);
    k_f23<<<dim3(S / 64, B), 256, F23_SMEM>>>(b1, b2, out);
}

// round 8
// speedup vs baseline: 1.2154x; 1.2154x over previous
#include <cuda_runtime.h>
#include <cuda.h>
#include <cuda_fp16.h>
#include <math.h>
#include <stdint.h>

#define B 8
#define S 8192
#define H 256
#define M 64
#define DFT_KS 16
#define DFT_CH (S / DFT_KS)   // 512

// ---------------- scratch (device globals) ----------------
__device__ float2 g_ph[S];
__device__ __half g_bfh[128 * S];     // DFT basis hi  [m'][t]
__device__ __half g_bfl[128 * S];     // DFT basis lo
__device__ __half g_ubh[B * S * H];   // u hi  [b][t][h]
__device__ __half g_ubl[B * S * H];   // u lo
__device__ __half g_b2[S * 128];      // iDFT basis single [t][0:64 cos,64:128 -sin]
__device__ __half g_cvh[B * H * 128]; // conv^T hi [b][h][0:64 re,64:128 im]
__device__ __half g_cvl[B * H * 128];
__device__ __half g_skwh[H * H], g_skwl[H * H];
__device__ __half g_w1h[128 * H], g_w1l[128 * H];
__device__ __half g_w2h[H * 128], g_w2l[H * 128];
__device__ __half g_act[B * S * H];   // gelu(conv+skip) single fp16
__device__ float  g_utr[B*M*H], g_uti[B*M*H];
__device__ float  g_sr [B*M*H], g_si [B*M*H];
__device__ float  g_part[B * 2 * DFT_KS * 16384];
__device__ float  g_mgr[64*2*4*1024], g_mgi[64*2*4*1024];

// ---------------- helpers ----------------
__device__ __forceinline__ void fma2(float2 &d, float2 a, float2 b) {
    asm("fma.rn.f32x2 %0, %1, %2, %0;"
        : "+l"(*reinterpret_cast<unsigned long long *>(&d))
        : "l"(*reinterpret_cast<unsigned long long *>(&a)),
          "l"(*reinterpret_cast<unsigned long long *>(&b)));
}
__device__ __forceinline__ float gelu(float x) {
    return 0.5f * x * (1.0f + erff(x * 0.70710678118654752f));
}
__device__ __forceinline__ uint32_t smem_u32(const void* p) {
    uint32_t a; asm("{ .reg .u64 t; cvta.to.shared.u64 t, %1; cvt.u32.u64 %0, t; }" : "=r"(a) : "l"(p));
    return a;
}
__device__ __forceinline__ void mma_f16(float c[4], const uint32_t a[4], uint32_t b0, uint32_t b1) {
    asm volatile("mma.sync.aligned.m16n8k16.row.col.f32.f16.f16.f32 "
        "{%0,%1,%2,%3}, {%4,%5,%6,%7}, {%8,%9}, {%0,%1,%2,%3};"
        : "+f"(c[0]), "+f"(c[1]), "+f"(c[2]), "+f"(c[3])
        : "r"(a[0]), "r"(a[1]), "r"(a[2]), "r"(a[3]), "r"(b0), "r"(b1));
}
#define LDSM_X4(r, addr) \
    asm volatile("ldmatrix.sync.aligned.m8n8.x4.shared.b16 {%0,%1,%2,%3}, [%4];" \
        : "=r"((r)[0]), "=r"((r)[1]), "=r"((r)[2]), "=r"((r)[3]) : "r"(addr))
#define LDSM_X4_T(r, addr) \
    asm volatile("ldmatrix.sync.aligned.m8n8.x4.trans.shared.b16 {%0,%1,%2,%3}, [%4];" \
        : "=r"((r)[0]), "=r"((r)[1]), "=r"((r)[2]), "=r"((r)[3]) : "r"(addr))
#define CPA16(dst, src) \
    asm volatile("cp.async.cg.shared.global [%0], [%1], 16;" :: "r"(dst), "l"(src) : "memory")

// 3-pass (DFT): (ah+al)(bh+bl) ~= ahbh + ahbl + albh
__device__ __forceinline__ void mma3(float c[4], const uint32_t ah[4], const uint32_t al[4],
                                     uint32_t bh0, uint32_t bh1, uint32_t bl0, uint32_t bl1) {
    mma_f16(c, ah, bh0, bh1);
    mma_f16(c, ah, bl0, bl1);
    mma_f16(c, al, bh0, bh1);
}
// 2-pass (GEMMs): a_single * (bh + bl)
__device__ __forceinline__ void mma2(float c[4], const uint32_t a[4],
                                     uint32_t bh0, uint32_t bh1, uint32_t bl0, uint32_t bl1) {
    mma_f16(c, a, bh0, bh1);
    mma_f16(c, a, bl0, bl1);
}
__device__ __forceinline__ void split_h(float v, __half &hi, __half &lo) {
    hi = __float2half_rn(v);
    lo = __float2half_rn(v - __half2float(hi));
}
__device__ __forceinline__ uint32_t pack2h(__half a, __half b) {
    return (uint32_t)__half_as_ushort(a) | ((uint32_t)__half_as_ushort(b) << 16);
}

// ---------------- K0: tables ----------------
__global__ void k_phase() {
    int p = blockIdx.x * 256 + threadIdx.x;
    if (p >= S) return;
    float ang = (float)p * (6.283185307179586f / 8192.0f);
    float sn, cn; sincosf(ang, &sn, &cn);
    g_ph[p] = make_float2(cn, sn);
}
__global__ void k_basisF() {
    int idx = blockIdx.x * 256 + threadIdx.x;
    int mp = idx >> 13, t = idx & 8191;
    float v;
    if (mp < 64) v =  g_ph[(mp * t) & 8191].x;
    else         v = -g_ph[((mp - 64) * t) & 8191].y;
    __half hi, lo; split_h(v, hi, lo);
    g_bfh[idx] = hi; g_bfl[idx] = lo;
}
__global__ void k_basis2() {
    int idx = blockIdx.x * 256 + threadIdx.x;
    if (idx >= S * 128) return;
    int t = idx >> 7, m = idx & 127;
    float v;
    if (m < 64) v =  g_ph[(t * m) & (S - 1)].x;
    else        v = -g_ph[(t * (m - 64)) & (S - 1)].y;
    g_b2[idx] = __float2half_rn(v);
}
__global__ void k_wsplit(const float *__restrict__ skw, const float *__restrict__ w1,
                         const float *__restrict__ w2) {
    int idx = blockIdx.x * 256 + threadIdx.x;   // < 131072
    float v; __half *dh, *dl; int o;
    if (idx < 65536)      { v = skw[idx];        dh = g_skwh; dl = g_skwl; o = idx; }
    else if (idx < 98304) { o = idx - 65536; v = w1[o]; dh = g_w1h; dl = g_w1l; }
    else                  { o = idx - 98304; v = w2[o]; dh = g_w2h; dl = g_w2l; }
    __half hi, lo; split_h(v, hi, lo);
    dh[o] = hi; dl[o] = lo;
}

// ---------------- u -> fp16 hi/lo ----------------
__global__ void k_usplit(const float *__restrict__ u) {
    size_t gid = (size_t)blockIdx.x * 256 + threadIdx.x;
    float4 v = ((const float4 *)u)[gid];
    float vv[4] = {v.x, v.y, v.z, v.w};
    uint32_t hh[2] = {0, 0}, ll[2] = {0, 0};
#pragma unroll
    for (int j = 0; j < 4; j++) {
        __half hi, lo; split_h(vv[j], hi, lo);
        hh[j >> 1] |= (uint32_t)__half_as_ushort(hi) << ((j & 1) * 16);
        ll[j >> 1] |= (uint32_t)__half_as_ushort(lo) << ((j & 1) * 16);
    }
    ((uint2 *)g_ubh)[gid] = make_uint2(hh[0], hh[1]);
    ((uint2 *)g_ubl)[gid] = make_uint2(ll[0], ll[1]);
}

// ---------------- DFT via fp16 3-pass mma + ldmatrix (structure proven) ----------------
#define DBUF 37888
#define DFT_SMEM (2 * DBUF)

__global__ void __launch_bounds__(256, 2) k_dftmma() {
    extern __shared__ __align__(16) char sm[];
    int tid = threadIdx.x, lane = tid & 31, w = tid >> 5;
    int wm = w & 3, wn = w >> 2, g = lane >> 2, tg = lane & 3;
    int ks = blockIdx.x, nb = blockIdx.y, b = blockIdx.z;
    int tbase0 = ks * DFT_CH;
    uint32_t s0 = smem_u32(sm);

    float acc[2][8][4];
#pragma unroll
    for (int mt = 0; mt < 2; mt++)
#pragma unroll
        for (int nt = 0; nt < 8; nt++)
#pragma unroll
            for (int q = 0; q < 4; q++) acc[mt][nt][q] = 0.f;

    auto stage = [&](int c, int buf) {
        int t0 = tbase0 + c * 32;
        uint32_t base = s0 + buf * DBUF;
#pragma unroll
        for (int it = 0; it < 2; it++) {
            int idx = it * 256 + tid;
            int r = idx >> 2, seg = idx & 3;
            uint32_t sh = base + (uint32_t)(r * 80 + seg * 16);
            CPA16(sh,         g_bfh + (size_t)r * S + t0 + seg * 8);
            CPA16(sh + 10240, g_bfl + (size_t)r * S + t0 + seg * 8);
        }
#pragma unroll
        for (int it = 0; it < 2; it++) {
            int idx = it * 256 + tid;
            int r = idx >> 4, seg = idx & 15;
            uint32_t sh = base + 20480 + (uint32_t)(r * 272 + seg * 16);
            CPA16(sh,        g_ubh + ((size_t)(b * S + t0 + r)) * 256 + nb * 128 + seg * 8);
            CPA16(sh + 8704, g_ubl + ((size_t)(b * S + t0 + r)) * 256 + nb * 128 + seg * 8);
        }
    };

    stage(0, 0);
    asm volatile("cp.async.commit_group;" ::: "memory");

    for (int c = 0; c < 16; c++) {
        int buf = c & 1;
        if (c < 15) {
            stage(c + 1, buf ^ 1);
            asm volatile("cp.async.commit_group;" ::: "memory");
            asm volatile("cp.async.wait_group 1;" ::: "memory");
        } else {
            asm volatile("cp.async.wait_group 0;" ::: "memory");
        }
        __syncthreads();

        uint32_t base = s0 + buf * DBUF;
#pragma unroll
        for (int kh = 0; kh < 2; kh++) {
            uint32_t ah[2][4], al[2][4];
#pragma unroll
            for (int mt = 0; mt < 2; mt++) {
                uint32_t ra = base + (uint32_t)((wm * 32 + mt * 16 + (lane & 15)) * 80 + kh * 32 + (lane >> 4) * 16);
                LDSM_X4(ah[mt], ra);
                LDSM_X4(al[mt], ra + 10240);
            }
#pragma unroll
            for (int ntp = 0; ntp < 4; ntp++) {
                uint32_t rb = base + 20480 +
                    (uint32_t)((kh * 16 + (lane & 7) + ((lane >> 3) & 1) * 8) * 272 +
                               (wn * 64 + ntp * 16 + (lane >> 4) * 8) * 2);
                uint32_t bh[4], bl[4];
                LDSM_X4_T(bh, rb);
                LDSM_X4_T(bl, rb + 8704);
#pragma unroll
                for (int mt = 0; mt < 2; mt++) {
                    mma3(acc[mt][2 * ntp],     ah[mt], al[mt], bh[0], bh[1], bl[0], bl[1]);
                    mma3(acc[mt][2 * ntp + 1], ah[mt], al[mt], bh[2], bh[3], bl[2], bl[3]);
                }
            }
        }
        __syncthreads();
    }

    float *pp = g_part + (size_t)((b * 2 + nb) * DFT_KS + ks) * 16384;
#pragma unroll
    for (int mt = 0; mt < 2; mt++)
#pragma unroll
        for (int nt = 0; nt < 8; nt++) {
            int row = wm * 32 + mt * 16 + g;
            int col = wn * 64 + nt * 8 + 2 * tg;
            *(float2 *)(pp + row * 128 + col)       = make_float2(acc[mt][nt][0], acc[mt][nt][1]);
            *(float2 *)(pp + (row + 8) * 128 + col) = make_float2(acc[mt][nt][2], acc[mt][nt][3]);
        }
}

__global__ void k_dftred() {
    int gid = blockIdx.x * 256 + threadIdx.x;
    int h = gid & 255, row = (gid >> 8) & 127, b = gid >> 15;
    int nb = h >> 7, cl = h & 127;
    const float *p = g_part + (size_t)((b * 2 + nb) * DFT_KS) * 16384 + row * 128 + cl;
    float s = 0.f;
#pragma unroll
    for (int ks = 0; ks < DFT_KS; ks++) s += p[(size_t)ks * 16384];
    if (row < 64) g_utr[(b * 64 + row) * 256 + h] = s;
    else          g_uti[(b * 64 + row - 64) * 256 + h] = s;
}

// ---------------- K2: per-mode complex GEMM (split-K x4) + reduce/GELU ----------------
__global__ void __launch_bounds__(256) k_modegemm(const float *__restrict__ Wr,
                                                  const float *__restrict__ Wi) {
    __shared__ float utr_s[8][256];
    __shared__ float uti_s[8][256];
    int m = blockIdx.x, half = blockIdx.y, kk = blockIdx.z;
    int tid = threadIdx.x;
#pragma unroll
    for (int i = 0; i < 8; i++) {
        int lin = i * 256 + tid; int bb = lin >> 8, h = lin & 255;
        utr_s[bb][h] = g_utr[(bb * 64 + m) * 256 + h];
        uti_s[bb][h] = g_uti[(bb * 64 + m) * 256 + h];
    }
    __syncthreads();
    int ho = half * 128 + (tid & 127);
    int bg = (tid >> 7) * 4;
    float accr[4] = {0,0,0,0}, acci[4] = {0,0,0,0};
    const float *wrp = Wr + (size_t)m * 65536 + ho;
    const float *wip = Wi + (size_t)m * 65536 + ho;
    int hk0 = kk * 64;
#pragma unroll 8
    for (int hk = hk0; hk < hk0 + 64; hk++) {
        float wr = wrp[(size_t)hk * 256], wi = wip[(size_t)hk * 256];
#pragma unroll
        for (int ib = 0; ib < 4; ib++) {
            float ur = utr_s[bg + ib][hk], ui = uti_s[bg + ib][hk];
            accr[ib] += ur * wr - ui * wi;
            acci[ib] += ur * wi + ui * wr;
        }
    }
    float *pr = g_mgr + (size_t)(((m * 2 + half) * 4) + kk) * 1024;
    float *pi = g_mgi + (size_t)(((m * 2 + half) * 4) + kk) * 1024;
#pragma unroll
    for (int ib = 0; ib < 4; ib++) {
        pr[(bg + ib) * 128 + (tid & 127)] = accr[ib];
        pi[(bg + ib) * 128 + (tid & 127)] = acci[ib];
    }
}

__global__ void k_mgred() {
    int gid = blockIdx.x * 256 + threadIdx.x;
    int h = gid & 255, m = (gid >> 8) & 63, b = gid >> 14;
    int half = h >> 7, ho = h & 127;
    size_t base = (size_t)((m * 2 + half) * 4) * 1024 + b * 128 + ho;
    float sr = 0.f, si = 0.f;
#pragma unroll
    for (int kk = 0; kk < 4; kk++) { sr += g_mgr[base + kk * 1024]; si += g_mgi[base + kk * 1024]; }
    g_sr[gid] = gelu(sr);
    g_si[gid] = gelu(si);
}

// ---------------- K3: circular convolution -> cvt hi/lo fp16 ----------------
__global__ void __launch_bounds__(256) k_conv() {
    __shared__ __align__(16) float utr_s[64][32];
    __shared__ __align__(16) float uti_s[64][32];
    __shared__ __align__(16) float sr_s[64][32];
    __shared__ __align__(16) float si_s[64][32];
    int b = blockIdx.x, ht = blockIdx.y;
    int h0 = ht * 32;
    int tid = threadIdx.x;
#pragma unroll
    for (int i = 0; i < 8; i++) {
        int lin = i * 256 + tid; int k = lin >> 5, hh = lin & 31;
        int o = (b * 64 + k) * 256 + h0 + hh;
        utr_s[k][hh] = g_utr[o]; uti_s[k][hh] = g_uti[o];
        sr_s[k][hh]  = g_sr[o];  si_s[k][hh]  = g_si[o];
    }
    __syncthreads();
    int m0 = (tid >> 4) << 2;
    int hp = tid & 15;
    float2 cr[4], ci[4];
#pragma unroll
    for (int i = 0; i < 4; i++) { cr[i] = make_float2(0.f,0.f); ci[i] = make_float2(0.f,0.f); }
    for (int k = 0; k < 64; k++) {
        float2 ua = ((float2 *)utr_s[k])[hp];
        float2 ub = ((float2 *)uti_s[k])[hp];
#pragma unroll
        for (int im = 0; im < 4; im++) {
            int j = ((m0 + im) - k) & 63;
            float2 br = ((float2 *)sr_s[j])[hp];
            float2 bi = ((float2 *)si_s[j])[hp];
            float2 nbi = make_float2(-bi.x, -bi.y);
            fma2(cr[im], ua, br);  fma2(cr[im], ub, nbi);
            fma2(ci[im], ua, bi);  fma2(ci[im], ub, br);
        }
    }
    const float SC = 1.0f / 65536.0f;
    int hA = h0 + 2 * hp, hB = hA + 1;
#pragma unroll
    for (int im = 0; im < 4; im++) {
        int m = m0 + im;
        float vals[4] = {cr[im].x * SC, cr[im].y * SC, ci[im].x * SC, ci[im].y * SC};
        int idxs[4] = {(b * 256 + hA) * 128 + m, (b * 256 + hB) * 128 + m,
                       (b * 256 + hA) * 128 + 64 + m, (b * 256 + hB) * 128 + 64 + m};
#pragma unroll
        for (int q = 0; q < 4; q++) {
            __half hi, lo; split_h(vals[q], hi, lo);
            g_cvh[idxs[q]] = hi; g_cvl[idxs[q]] = lo;
        }
    }
}

// ---------------- G1: iDFT + skip, fp16 2-pass (A single, B hi/lo) ----------------
// per buffer: A@0 (10240), Bh@10240 (10240), Bl@20480 (10240) => 30720
#define G1BUF 30720
#define G1_SMEM (2 * G1BUF)

__global__ void __launch_bounds__(256, 2) k_g1(const float *__restrict__ skb) {
    extern __shared__ __align__(16) char sm[];
    int tid = threadIdx.x, lane = tid & 31, w = tid >> 5;
    int wm = w & 3, wn = w >> 2, g = lane >> 2, tg = lane & 3;
    int t0 = blockIdx.x * 128, n0 = blockIdx.y * 128, b = blockIdx.z;
    uint32_t s0 = smem_u32(sm);

    float acc[2][8][4];
#pragma unroll
    for (int mt = 0; mt < 2; mt++)
#pragma unroll
        for (int nt = 0; nt < 8; nt++)
#pragma unroll
            for (int q = 0; q < 4; q++) acc[mt][nt][q] = 0.f;

    auto stage = [&](int c, int buf) {
        uint32_t base = s0 + buf * G1BUF;
#pragma unroll
        for (int it = 0; it < 2; it++) {        // A single: 128 rows x 4 segs
            int idx = it * 256 + tid;
            int r = idx >> 2, seg = idx & 3;
            uint32_t sh = base + (uint32_t)(r * 80 + seg * 16);
            const __half *ga = (c < 4)
                ? g_b2 + (size_t)(t0 + r) * 128 + c * 32 + seg * 8
                : g_ubh + ((size_t)(b * S + t0 + r)) * 256 + (c - 4) * 32 + seg * 8;
            CPA16(sh, ga);
        }
#pragma unroll
        for (int it = 0; it < 2; it++) {        // B hi/lo: 128 rows x 4 segs
            int idx = it * 256 + tid;
            int r = idx >> 2, seg = idx & 3;
            uint32_t sh = base + 10240 + (uint32_t)(r * 80 + seg * 16);
            const __half *gh, *gl;
            if (c < 4) {
                gh = g_cvh + (size_t)(b * 256 + n0 + r) * 128 + c * 32 + seg * 8;
                gl = g_cvl + (size_t)(b * 256 + n0 + r) * 128 + c * 32 + seg * 8;
            } else {
                gh = g_skwh + (size_t)(n0 + r) * 256 + (c - 4) * 32 + seg * 8;
                gl = g_skwl + (size_t)(n0 + r) * 256 + (c - 4) * 32 + seg * 8;
            }
            CPA16(sh, gh); CPA16(sh + 10240, gl);
        }
    };

    stage(0, 0);
    asm volatile("cp.async.commit_group;" ::: "memory");

    for (int c = 0; c < 12; c++) {
        int buf = c & 1;
        if (c < 11) {
            stage(c + 1, buf ^ 1);
            asm volatile("cp.async.commit_group;" ::: "memory");
            asm volatile("cp.async.wait_group 1;" ::: "memory");
        } else {
            asm volatile("cp.async.wait_group 0;" ::: "memory");
        }
        __syncthreads();

        uint32_t base = s0 + buf * G1BUF;
#pragma unroll
        for (int kh = 0; kh < 2; kh++) {
            uint32_t as[2][4];
#pragma unroll
            for (int mt = 0; mt < 2; mt++) {
                uint32_t ra = base + (uint32_t)((wm * 32 + mt * 16 + (lane & 15)) * 80 + kh * 32 + (lane >> 4) * 16);
                LDSM_X4(as[mt], ra);
            }
#pragma unroll
            for (int nq = 0; nq < 4; nq++) {
                uint32_t rb = base + 10240 +
                    (uint32_t)((wn * 64 + nq * 16 + (lane & 7) + ((lane >> 4) & 1) * 8) * 80 +
                               kh * 32 + ((lane >> 3) & 1) * 16);
                uint32_t bh[4], bl[4];
                LDSM_X4(bh, rb);
                LDSM_X4(bl, rb + 10240);
#pragma unroll
                for (int mt = 0; mt < 2; mt++) {
                    mma2(acc[mt][2 * nq],     as[mt], bh[0], bh[1], bl[0], bl[1]);
                    mma2(acc[mt][2 * nq + 1], as[mt], bh[2], bh[3], bl[2], bl[3]);
                }
            }
        }
        __syncthreads();
    }

    // epilogue: gelu(+skb) -> act single fp16
#pragma unroll
    for (int mt = 0; mt < 2; mt++)
#pragma unroll
        for (int nt = 0; nt < 8; nt++) {
            int row = t0 + wm * 32 + mt * 16 + g;
            int col = n0 + wn * 64 + nt * 8 + 2 * tg;
            float bz0 = __ldg(skb + col), bz1 = __ldg(skb + col + 1);
            float v0 = gelu(acc[mt][nt][0] + bz0), v1 = gelu(acc[mt][nt][1] + bz1);
            float v2 = gelu(acc[mt][nt][2] + bz0), v3 = gelu(acc[mt][nt][3] + bz1);
            size_t o0 = ((size_t)(b * S) + row) * 256 + col;
            size_t o1 = ((size_t)(b * S) + row + 8) * 256 + col;
            *(uint32_t *)(g_act + o0) = pack2h(__float2half_rn(v0), __float2half_rn(v1));
            *(uint32_t *)(g_act + o1) = pack2h(__float2half_rn(v2), __float2half_rn(v3));
        }
}

// ---------------- fused G2+G3, fp16 2-pass ----------------
// hsm single @0 (17408B = 64 rows x 272B); buffers @17408 + buf*25600:
//   A@0 (5120), Bh@5120 (10240), Bl@15360 (10240)
#define F23_BUF0 17408
#define F23_BUFSZ 25600
#define F23_SMEM (F23_BUF0 + 2 * F23_BUFSZ)   // 68608

__global__ void __launch_bounds__(256, 2) k_f23(
    const float *__restrict__ b1, const float *__restrict__ b2,
    float *__restrict__ out) {
    extern __shared__ __align__(16) char sm[];
    int tid = threadIdx.x, lane = tid & 31, w = tid >> 5;
    int wm = w & 1, wn = w >> 1;            // 2 (m) x 4 (n)
    int g = lane >> 2, tg = lane & 3;
    int t0 = blockIdx.x * 64, b = blockIdx.y;
    uint32_t s0 = smem_u32(sm);
    uint32_t hs = s0;                        // h single, stride 272B

    float acc[2][4][4];
#pragma unroll
    for (int mt = 0; mt < 2; mt++)
#pragma unroll
        for (int nt = 0; nt < 4; nt++)
#pragma unroll
            for (int q = 0; q < 4; q++) acc[mt][nt][q] = 0.f;

    // ---------- G2: h = gelu(act @ w1^T + b1) ----------
    auto stage2 = [&](int c, int buf) {
        uint32_t base = s0 + F23_BUF0 + buf * F23_BUFSZ;
        {   // A: act 64 rows x 4 segs (single)
            int r = tid >> 2, seg = tid & 3;
            uint32_t sh = base + (uint32_t)(r * 80 + seg * 16);
            CPA16(sh, g_act + ((size_t)(b * S + t0 + r)) * 256 + c * 32 + seg * 8);
        }
#pragma unroll
        for (int it = 0; it < 2; it++) {     // B: w1 128 rows hi/lo
            int idx = it * 256 + tid;
            int r = idx >> 2, seg = idx & 3;
            uint32_t sh = base + 5120 + (uint32_t)(r * 80 + seg * 16);
            size_t go = (size_t)r * 256 + c * 32 + seg * 8;
            CPA16(sh, g_w1h + go); CPA16(sh + 10240, g_w1l + go);
        }
    };

    stage2(0, 0);
    asm volatile("cp.async.commit_group;" ::: "memory");
    for (int c = 0; c < 8; c++) {
        int buf = c & 1;
        if (c < 7) {
            stage2(c + 1, buf ^ 1);
            asm volatile("cp.async.commit_group;" ::: "memory");
            asm volatile("cp.async.wait_group 1;" ::: "memory");
        } else {
            asm volatile("cp.async.wait_group 0;" ::: "memory");
        }
        __syncthreads();
        uint32_t base = s0 + F23_BUF0 + buf * F23_BUFSZ;
#pragma unroll
        for (int kh = 0; kh < 2; kh++) {
            uint32_t as[2][4];
#pragma unroll
            for (int mt = 0; mt < 2; mt++) {
                uint32_t ra = base + (uint32_t)((wm * 32 + mt * 16 + (lane & 15)) * 80 + kh * 32 + (lane >> 4) * 16);
                LDSM_X4(as[mt], ra);
            }
#pragma unroll
            for (int nq = 0; nq < 2; nq++) {
                uint32_t rb = base + 5120 +
                    (uint32_t)((wn * 32 + nq * 16 + (lane & 7) + ((lane >> 4) & 1) * 8) * 80 +
                               kh * 32 + ((lane >> 3) & 1) * 16);
                uint32_t bh[4], bl[4];
                LDSM_X4(bh, rb);
                LDSM_X4(bl, rb + 10240);
#pragma unroll
                for (int mt = 0; mt < 2; mt++) {
                    mma2(acc[mt][2 * nq],     as[mt], bh[0], bh[1], bl[0], bl[1]);
                    mma2(acc[mt][2 * nq + 1], as[mt], bh[2], bh[3], bl[2], bl[3]);
                }
            }
        }
        __syncthreads();
    }
    // epilogue G2 -> h single fp16 in smem (stride 272B)
#pragma unroll
    for (int mt = 0; mt < 2; mt++)
#pragma unroll
        for (int nt = 0; nt < 4; nt++) {
            int row = wm * 32 + mt * 16 + g;
            int col = wn * 32 + nt * 8 + 2 * tg;
            float bz0 = __ldg(b1 + col), bz1 = __ldg(b1 + col + 1);
            float v0 = gelu(acc[mt][nt][0] + bz0), v1 = gelu(acc[mt][nt][1] + bz1);
            float v2 = gelu(acc[mt][nt][2] + bz0), v3 = gelu(acc[mt][nt][3] + bz1);
            uint32_t o0 = (uint32_t)(row * 272 + col * 2);
            uint32_t o1 = (uint32_t)((row + 8) * 272 + col * 2);
            asm volatile("st.shared.b32 [%0], %1;" :: "r"(hs + o0),
                         "r"(pack2h(__float2half_rn(v0), __float2half_rn(v1))));
            asm volatile("st.shared.b32 [%0], %1;" :: "r"(hs + o1),
                         "r"(pack2h(__float2half_rn(v2), __float2half_rn(v3))));
        }
    __syncthreads();

    // ---------- G3: out = h @ w2^T + b2, two 128-col halves ----------
    for (int nh = 0; nh < 2; nh++) {
        auto stage3 = [&](int c, int buf) {
            uint32_t base = s0 + F23_BUF0 + buf * F23_BUFSZ;
#pragma unroll
            for (int it = 0; it < 2; it++) {
                int idx = it * 256 + tid;
                int r = idx >> 2, seg = idx & 3;
                uint32_t sh = base + 5120 + (uint32_t)(r * 80 + seg * 16);
                size_t go = (size_t)(nh * 128 + r) * 128 + c * 32 + seg * 8;
                CPA16(sh, g_w2h + go); CPA16(sh + 10240, g_w2l + go);
            }
        };
#pragma unroll
        for (int mt = 0; mt < 2; mt++)
#pragma unroll
            for (int nt = 0; nt < 4; nt++)
#pragma unroll
                for (int q = 0; q < 4; q++) acc[mt][nt][q] = 0.f;

        stage3(0, 0);
        asm volatile("cp.async.commit_group;" ::: "memory");
        for (int c = 0; c < 4; c++) {
            int buf = c & 1;
            if (c < 3) {
                stage3(c + 1, buf ^ 1);
                asm volatile("cp.async.commit_group;" ::: "memory");
                asm volatile("cp.async.wait_group 1;" ::: "memory");
            } else {
                asm volatile("cp.async.wait_group 0;" ::: "memory");
            }
            __syncthreads();
            uint32_t base = s0 + F23_BUF0 + buf * F23_BUFSZ;
#pragma unroll
            for (int kh = 0; kh < 2; kh++) {
                uint32_t as[2][4];
#pragma unroll
                for (int mt = 0; mt < 2; mt++) {
                    uint32_t ra = (uint32_t)((wm * 32 + mt * 16 + (lane & 15)) * 272 +
                                             c * 64 + kh * 32 + (lane >> 4) * 16);
                    LDSM_X4(as[mt], hs + ra);
                }
#pragma unroll
                for (int nq = 0; nq < 2; nq++) {
                    uint32_t rb = base + 5120 +
                        (uint32_t)((wn * 32 + nq * 16 + (lane & 7) + ((lane >> 4) & 1) * 8) * 80 +
                                   kh * 32 + ((lane >> 3) & 1) * 16);
                    uint32_t bh[4], bl[4];
                    LDSM_X4(bh, rb);
                    LDSM_X4(bl, rb + 10240);
#pragma unroll
                    for (int mt = 0; mt < 2; mt++) {
                        mma2(acc[mt][2 * nq],     as[mt], bh[0], bh[1], bl[0], bl[1]);
                        mma2(acc[mt][2 * nq + 1], as[mt], bh[2], bh[3], bl[2], bl[3]);
                    }
                }
            }
            __syncthreads();
        }
        // epilogue G3 -> out
#pragma unroll
        for (int mt = 0; mt < 2; mt++)
#pragma unroll
            for (int nt = 0; nt < 4; nt++) {
                int row = t0 + wm * 32 + mt * 16 + g;
                int col = nh * 128 + wn * 32 + nt * 8 + 2 * tg;
                float bz0 = __ldg(b2 + col), bz1 = __ldg(b2 + col + 1);
                float2 v0 = make_float2(acc[mt][nt][0] + bz0, acc[mt][nt][1] + bz1);
                float2 v1 = make_float2(acc[mt][nt][2] + bz0, acc[mt][nt][3] + bz1);
                *(float2 *)(out + ((size_t)b * S + row) * 256 + col)     = v0;
                *(float2 *)(out + ((size_t)b * S + row + 8) * 256 + col) = v1;
            }
        __syncthreads();
    }
}

// ---------------- launch ----------------
extern "C" void kernel_launch(void *const *d_in, const int *in_sizes, int n_in,
                              void *d_out, int out_size) {
    const float *u   = (const float *)d_in[0];
    const float *Wr  = (const float *)d_in[1];
    const float *Wi  = (const float *)d_in[2];
    const float *skw = (const float *)d_in[3];
    const float *skb = (const float *)d_in[4];
    const float *w1  = (const float *)d_in[5];
    const float *b1  = (const float *)d_in[6];
    const float *w2  = (const float *)d_in[7];
    const float *b2  = (const float *)d_in[8];
    float *out = (float *)d_out;

    cudaFuncSetAttribute(k_dftmma, cudaFuncAttributeMaxDynamicSharedMemorySize, DFT_SMEM);
    cudaFuncSetAttribute(k_g1, cudaFuncAttributeMaxDynamicSharedMemorySize, G1_SMEM);
    cudaFuncSetAttribute(k_f23, cudaFuncAttributeMaxDynamicSharedMemorySize, F23_SMEM);

    k_phase<<<(S + 255) / 256, 256>>>();
    k_basisF<<<(128 * S) / 256, 256>>>();
    k_basis2<<<(S * 128) / 256, 256>>>();
    k_usplit<<<(B * S * H / 4) / 256, 256>>>(u);
    k_wsplit<<<512, 256>>>(skw, w1, w2);
    k_dftmma<<<dim3(DFT_KS, 2, B), 256, DFT_SMEM>>>();
    k_dftred<<<(B * 128 * 256) / 256, 256>>>();
    k_modegemm<<<dim3(M, 2, 4), 256>>>(Wr, Wi);
    k_mgred<<<(B * M * H) / 256, 256>>>();
    k_conv<<<dim3(B, 8), 256>>>();
    k_g1<<<dim3(S / 128, 2, B), 256, G1_SMEM>>>(skb);
    k_f23<<<dim3(S / 64, B), 256, F23_SMEM>>>(b1, b2, out);
}